// round 11
// baseline (speedup 1.0000x reference)
#include <cuda_runtime.h>

#define SLEN 4096
#define NBATCH 8
#define TOK (NBATCH*SLEN)
#define EMB 1024
#define HD 64
#define HALF 32

// Scratch (device globals: allocation-free rule)
__device__ float g_K[TOK*HD];
__device__ float g_Q[TOK*HD];
__device__ float g_V[TOK*HD];
__device__ unsigned short g_W1h[96*1024];   // W1 transposed [n=p*32+h][k], bf16 hi
__device__ unsigned short g_W1l[96*1024];   // lo residual
__device__ unsigned short g_W2h[192*32];    // W2 transposed [p*64+h][j], bf16 hi
__device__ unsigned short g_W2l[192*32];

// ---------- helpers ----------
__device__ __forceinline__ unsigned smem_u32(const void* p) {
    unsigned a;
    asm("{ .reg .u64 t; cvta.to.shared.u64 t, %1; cvt.u32.u64 %0, t; }" : "=r"(a) : "l"(p));
    return a;
}
__device__ __forceinline__ float ex2f(float x) {
    float r;
    asm("ex2.approx.f32 %0, %1;" : "=f"(r) : "f"(x));
    return r;
}
// pack: result.hi = bf16(hi), result.lo = bf16(lo)
__device__ __forceinline__ unsigned bfpack(float hi, float lo) {
    unsigned d;
    asm("cvt.rn.bf16x2.f32 %0, %1, %2;" : "=r"(d) : "f"(hi), "f"(lo));
    return d;
}
// D(16x8,f32) += A(16x16 bf16) * B(16x8 bf16)
__device__ __forceinline__ void mma16(float* c, const unsigned* a, unsigned b0, unsigned b1) {
    asm("mma.sync.aligned.m16n8k16.row.col.f32.bf16.bf16.f32 "
        "{%0,%1,%2,%3}, {%4,%5,%6,%7}, {%8,%9}, {%0,%1,%2,%3};"
        : "+f"(c[0]), "+f"(c[1]), "+f"(c[2]), "+f"(c[3])
        : "r"(a[0]), "r"(a[1]), "r"(a[2]), "r"(a[3]), "r"(b0), "r"(b1));
}
__device__ __forceinline__ void ldm4(unsigned* r, unsigned addr) {
    asm volatile("ldmatrix.sync.aligned.m8n8.x4.shared.b16 {%0,%1,%2,%3}, [%4];"
                 : "=r"(r[0]), "=r"(r[1]), "=r"(r[2]), "=r"(r[3]) : "r"(addr));
}
__device__ __forceinline__ void ldm4t(unsigned* r, unsigned addr) {
    asm volatile("ldmatrix.sync.aligned.m8n8.x4.trans.shared.b16 {%0,%1,%2,%3}, [%4];"
                 : "=r"(r[0]), "=r"(r[1]), "=r"(r[2]), "=r"(r[3]) : "r"(addr));
}
__device__ __forceinline__ void st32(unsigned addr, unsigned v) {
    asm volatile("st.shared.b32 [%0], %1;" :: "r"(addr), "r"(v) : "memory");
}

// =========================================================================
// conv_w: one-time weight transpose + bf16 hi/lo split.
// =========================================================================
__global__ void conv_w(
    const float* __restrict__ wk1, const float* __restrict__ wq1, const float* __restrict__ wv1,
    const float* __restrict__ wk2, const float* __restrict__ wq2, const float* __restrict__ wv2)
{
    int i = blockIdx.x*blockDim.x + threadIdx.x;
    int stride = gridDim.x*blockDim.x;
    for (int idx = i; idx < 96*1024; idx += stride) {
        int n = idx >> 10, k = idx & 1023;
        int p = n >> 5, h = n & 31;
        const float* w1 = (p == 0) ? wk1 : ((p == 1) ? wq1 : wv1);
        float v = w1[k*HALF + h];
        unsigned hb = bfpack(0.f, v) & 0xFFFFu;
        float res = v - __uint_as_float(hb << 16);
        g_W1h[idx] = (unsigned short)hb;
        g_W1l[idx] = (unsigned short)(bfpack(0.f, res) & 0xFFFFu);
    }
    for (int idx = i; idx < 192*32; idx += stride) {
        int row = idx >> 5, j = idx & 31;
        int p = row >> 6, h = row & 63;
        const float* w2 = (p == 0) ? wk2 : ((p == 1) ? wq2 : wv2);
        float v = w2[j*HD + h];
        unsigned hb = bfpack(0.f, v) & 0xFFFFu;
        float res = v - __uint_as_float(hb << 16);
        g_W2h[idx] = (unsigned short)hb;
        g_W2l[idx] = (unsigned short)(bfpack(0.f, res) & 0xFFFFu);
    }
}

// =========================================================================
// proj_mma v2: double-buffered slab pipeline (1 sync/slab).
//   Buffers (2x40960B): XH+0, XL+8192, W1H+16384, W1L+28672.
//   W2 planes: W2H@81920, W2L@97280 (pitch 80B). Total 112640B; 2 CTAs/SM.
// =========================================================================
#define PBUF 40960
#define PW2H 81920
#define PW2L 97280
#define PSM_BYTES 112640

__device__ __forceinline__ void stage_slab(
    unsigned char* dsm, unsigned sb, unsigned bo,
    const float* __restrict__ x, int tok0, int s, int tid)
{
    const float4* gx = (const float4*)x;
#pragma unroll
    for (int it = 0; it < 8; it++) {
        int idx = tid + it*128;      // 1024 float4
        int row = idx >> 4, f = idx & 15;
        float4 v = gx[(long long)(tok0 + row)*256 + s*16 + f];
        unsigned h0 = bfpack(v.y, v.x);
        float r0 = v.x - __uint_as_float(h0 << 16);
        float r1 = v.y - __uint_as_float(h0 & 0xFFFF0000u);
        unsigned l0 = bfpack(r1, r0);
        unsigned h1 = bfpack(v.w, v.z);
        float r2 = v.z - __uint_as_float(h1 << 16);
        float r3 = v.w - __uint_as_float(h1 & 0xFFFF0000u);
        unsigned l1 = bfpack(r3, r2);
        unsigned off = bo + row*128 + ((((unsigned)(f >> 1)) ^ (unsigned)(row & 7)) << 4) + (f & 1)*8;
        st32(sb + off, h0);          st32(sb + off + 4, h1);
        st32(sb + 8192 + off, l0);   st32(sb + 8192 + off + 4, l1);
    }
#pragma unroll
    for (int it = 0; it < 6; it++) {
        int idx = tid + it*128;      // 768 uint4 per plane
        int row = idx >> 3, f = idx & 7;
        unsigned off = bo + 16384 + row*128 + (((unsigned)f ^ (unsigned)(row & 7)) << 4);
        *(uint4*)(dsm + off)         = *(const uint4*)(g_W1h + row*1024 + s*64 + 8*f);
        *(uint4*)(dsm + off + 12288) = *(const uint4*)(g_W1l + row*1024 + s*64 + 8*f);
    }
}

__global__ __launch_bounds__(128, 2) void proj_mma(
    const float* __restrict__ x,
    const float* __restrict__ bk1, const float* __restrict__ bq1, const float* __restrict__ bv1)
{
    extern __shared__ __align__(1024) unsigned char dsm[];
    const unsigned sb = smem_u32(dsm);

    const int tid = threadIdx.x;
    const int w    = tid >> 5;
    const int lane = tid & 31;
    const int g = lane >> 2, r = lane & 3;
    const int laneKey = lane & 15, laneHi = lane >> 4;
    const int tok0 = blockIdx.x * 64;

    // ---- stage W2t once (pitch 80B rows) ----
#pragma unroll
    for (int it = 0; it < 6; it++) {
        int idx = tid + it*128;              // 768 uint4 per plane
        int row = idx >> 2, f = idx & 3;
        *(uint4*)(dsm + PW2H + row*80 + f*16) = *(const uint4*)(g_W2h + row*32 + 8*f);
        *(uint4*)(dsm + PW2L + row*80 + f*16) = *(const uint4*)(g_W2l + row*32 + 8*f);
    }

    float Cf[12][4];
#pragma unroll
    for (int nt = 0; nt < 12; nt++)
#pragma unroll
        for (int u = 0; u < 4; u++) Cf[nt][u] = 0.f;

    // prime the pipeline
    stage_slab(dsm, sb, 0, x, tok0, 0, tid);

    for (int s = 0; s < 16; s++) {
        __syncthreads();                     // buf[s&1] staged; prior readers done
        const unsigned bo = (unsigned)(s & 1) * PBUF;

        // ---- GEMM1: Cf += X * W1t (3-term bf16 split) ----
#pragma unroll
        for (int c = 0; c < 4; c++) {
            unsigned axh[4], axl[4];
            unsigned adrA = sb + bo + (16*w + laneKey)*128
                          + ((((unsigned)(2*c + laneHi)) ^ (unsigned)(laneKey & 7)) << 4);
            ldm4(axh, adrA);
            ldm4(axl, adrA + 8192);
#pragma unroll
            for (int tp = 0; tp < 6; tp++) {
                unsigned adrB = sb + bo + 16384 + (16*tp + laneKey)*128
                              + ((((unsigned)(2*c + laneHi)) ^ (unsigned)(laneKey & 7)) << 4);
                unsigned bh[4], bl[4];
                ldm4(bh, adrB);
                ldm4(bl, adrB + 12288);
                mma16(Cf[2*tp],   axh, bh[0], bh[2]);
                mma16(Cf[2*tp],   axl, bh[0], bh[2]);
                mma16(Cf[2*tp],   axh, bl[0], bl[2]);
                mma16(Cf[2*tp+1], axh, bh[1], bh[3]);
                mma16(Cf[2*tp+1], axl, bh[1], bh[3]);
                mma16(Cf[2*tp+1], axh, bl[1], bl[3]);
            }
        }

        // ---- prefetch next slab into the other buffer ----
        if (s + 1 < 16)
            stage_slab(dsm, sb, (unsigned)((s + 1) & 1) * PBUF, x, tok0, s + 1, tid);
    }

    // ---- bias + tanh in registers ----
#pragma unroll
    for (int nt = 0; nt < 12; nt++) {
        int p = nt >> 2;
        int h0 = (nt & 3)*8 + 2*r;
        const float* b1 = (p == 0) ? bk1 : ((p == 1) ? bq1 : bv1);
        float bb0 = b1[h0], bb1 = b1[h0 + 1];
        Cf[nt][0] = tanhf(Cf[nt][0] + bb0);
        Cf[nt][1] = tanhf(Cf[nt][1] + bb1);
        Cf[nt][2] = tanhf(Cf[nt][2] + bb0);
        Cf[nt][3] = tanhf(Cf[nt][3] + bb1);
    }

    // ---- GEMM2: {K,Q,V} = H_p * W2t_p (H from registers) ----
#pragma unroll
    for (int p = 0; p < 3; p++) {
        float o2[8][4];
#pragma unroll
        for (int e = 0; e < 8; e++)
#pragma unroll
            for (int u = 0; u < 4; u++) o2[e][u] = 0.f;

#pragma unroll
        for (int kc = 0; kc < 2; kc++) {
            int nt0 = 4*p + 2*kc;
            unsigned ah[4], al[4];
#pragma unroll
            for (int u = 0; u < 4; u++) {
                int nt = nt0 + ((u & 2) ? 1 : 0);
                int v0 = (u & 1) ? 2 : 0;
                float pa = Cf[nt][v0], pb = Cf[nt][v0 + 1];
                unsigned hh = bfpack(pb, pa);
                ah[u] = hh;
                float ra = pa - __uint_as_float(hh << 16);
                float rb = pb - __uint_as_float(hh & 0xFFFF0000u);
                al[u] = bfpack(rb, ra);
            }
#pragma unroll
            for (int e2 = 0; e2 < 4; e2++) {
                unsigned adr = sb + PW2H + (p*64 + 16*e2 + laneKey)*80 + kc*32 + laneHi*16;
                unsigned bh[4], bl[4];
                ldm4(bh, adr);
                ldm4(bl, adr + (PW2L - PW2H));
                mma16(o2[2*e2],   ah, bh[0], bh[2]);
                mma16(o2[2*e2],   al, bh[0], bh[2]);
                mma16(o2[2*e2],   ah, bl[0], bl[2]);
                mma16(o2[2*e2+1], ah, bh[1], bh[3]);
                mma16(o2[2*e2+1], al, bh[1], bh[3]);
                mma16(o2[2*e2+1], ah, bl[1], bl[3]);
            }
        }

        float* gout = (p == 0) ? g_K : ((p == 1) ? g_Q : g_V);
        long long row0 = tok0 + 16*w + g;
#pragma unroll
        for (int e = 0; e < 8; e++) {
            int h0 = 8*e + 2*r;
            *(float2*)&gout[row0*HD + h0]       = make_float2(o2[e][0], o2[e][1]);
            *(float2*)&gout[(row0 + 8)*HD + h0] = make_float2(o2[e][2], o2[e][3]);
        }
    }
}

// =========================================================================
// attn_bf16 v2: double-buffered K/V pipeline (1 sync/tile).
//   Buffers (2x32768B): KHI+0, KLO+8192, VHI+16384, VLO+24576.
//   Dynamic smem 64KB; 3 CTAs/SM.
// =========================================================================
#define ABUF 32768
#define ASM_BYTES 65536

__device__ __forceinline__ void stage_kv(unsigned bufb, long long kbase, int tid)
{
    const float2* gk2 = (const float2*)(g_K + kbase);
    const float2* gv2 = (const float2*)(g_V + kbase);
#pragma unroll
    for (int it = 0; it < 16; it++) {
        int idx = tid + it*128;
        int key = idx >> 5, pr = idx & 31;
        unsigned off = key*128 + ((((unsigned)(pr >> 2)) ^ (unsigned)(key & 7)) << 4) + (pr & 3)*4;
        float2 kv = gk2[idx];
        unsigned hk = bfpack(kv.y, kv.x);
        st32(bufb + off, hk);
        float ka = kv.x - __uint_as_float(hk << 16);
        float kb2 = kv.y - __uint_as_float(hk & 0xFFFF0000u);
        st32(bufb + 8192 + off, bfpack(kb2, ka));
        float2 vv = gv2[idx];
        unsigned hv = bfpack(vv.y, vv.x);
        st32(bufb + 16384 + off, hv);
        float va = vv.x - __uint_as_float(hv << 16);
        float vb = vv.y - __uint_as_float(hv & 0xFFFF0000u);
        st32(bufb + 24576 + off, bfpack(vb, va));
    }
}

__global__ __launch_bounds__(128, 3) void attn_bf16(float* __restrict__ out)
{
    extern __shared__ __align__(1024) unsigned char asm_[];
    const unsigned sb = smem_u32(asm_);

    const int tid  = threadIdx.x;
    const int w    = tid >> 5;
    const int lane = tid & 31;
    const int g    = lane >> 2;
    const int r    = lane & 3;
    const int laneKey = lane & 15;
    const int laneHi  = lane >> 4;
    const int kx      = laneKey & 7;
    const unsigned lmBase = laneKey * 128;

    const int bid = blockIdx.x;
    const int b   = bid & 7;
    const int qt  = 63 - (bid >> 3);
    const int nk  = qt + 1;
    const long long tokb = (long long)b*SLEN;
    const long long qrow0 = tokb + (long long)qt*64;
    const int q0 = qt*64 + 16*w + g;
    const int q1 = q0 + 8;

    const float SC = 0.1803368801111204f;    // 1/sqrt(64) * log2(e)
    unsigned qhi[4][4], qlo[4][4];
    {
        const float* qA = g_Q + (qrow0 + 16*w + g)*HD;
        const float* qB = qA + 8*HD;
#pragma unroll
        for (int c = 0; c < 4; c++) {
#pragma unroll
            for (int u = 0; u < 4; u++) {
                const float* src = (u & 1) ? qB : qA;
                int d = 16*c + 2*r + ((u & 2) ? 8 : 0);
                float2 xv = *(const float2*)(src + d);
                float v0 = xv.x * SC, v1 = xv.y * SC;
                unsigned h = bfpack(v1, v0);
                qhi[c][u] = h;
                float r0 = v0 - __uint_as_float(h << 16);
                float r1 = v1 - __uint_as_float(h & 0xFFFF0000u);
                qlo[c][u] = bfpack(r1, r0);
            }
        }
    }

    float o[8][4];
#pragma unroll
    for (int j = 0; j < 8; j++)
#pragma unroll
        for (int u = 0; u < 4; u++) o[j][u] = 0.f;
    float l0 = 0.f, l1 = 0.f;

    // prime the pipeline
    stage_kv(sb, tokb * HD, tid);

    for (int kt = 0; kt < nk; kt++) {
        __syncthreads();                      // buf[kt&1] staged; old readers done
        const unsigned cur = sb + (unsigned)(kt & 1) * ABUF;
        const unsigned KHIb = cur, VHIb = cur + 16384;

        // ---- QK: S[16 x 64] via 3-term bf16 split ----
        float s[8][4];
#pragma unroll
        for (int j = 0; j < 8; j++)
#pragma unroll
            for (int u = 0; u < 4; u++) s[j][u] = 0.f;

#pragma unroll
        for (int c = 0; c < 4; c++) {
#pragma unroll
            for (int t = 0; t < 4; t++) {
                unsigned adr = KHIb + lmBase + t*2048 + ((((unsigned)(2*c + laneHi)) ^ (unsigned)kx) << 4);
                unsigned kh[4], kl[4];
                ldm4(kh, adr);
                ldm4(kl, adr + 8192);
                mma16(s[2*t],   qhi[c], kh[0], kh[2]);
                mma16(s[2*t],   qlo[c], kh[0], kh[2]);
                mma16(s[2*t],   qhi[c], kl[0], kl[2]);
                mma16(s[2*t+1], qhi[c], kh[1], kh[3]);
                mma16(s[2*t+1], qlo[c], kh[1], kh[3]);
                mma16(s[2*t+1], qhi[c], kl[1], kl[3]);
            }
        }

        // ---- softmax (p = 2^s, no-max) + causal mask ----
        const int kb = kt*64;
        if (kt == qt) {
#pragma unroll
            for (int j = 0; j < 8; j++) {
                int k0 = kb + 8*j + 2*r;
                float p0 = (k0     > q0) ? 0.f : ex2f(fminf(s[j][0], 80.f));
                float p1 = (k0 + 1 > q0) ? 0.f : ex2f(fminf(s[j][1], 80.f));
                float p2 = (k0     > q1) ? 0.f : ex2f(fminf(s[j][2], 80.f));
                float p3 = (k0 + 1 > q1) ? 0.f : ex2f(fminf(s[j][3], 80.f));
                l0 += p0 + p1; l1 += p2 + p3;
                s[j][0] = p0; s[j][1] = p1; s[j][2] = p2; s[j][3] = p3;
            }
        } else {
#pragma unroll
            for (int j = 0; j < 8; j++) {
                float p0 = ex2f(fminf(s[j][0], 80.f));
                float p1 = ex2f(fminf(s[j][1], 80.f));
                float p2 = ex2f(fminf(s[j][2], 80.f));
                float p3 = ex2f(fminf(s[j][3], 80.f));
                l0 += p0 + p1; l1 += p2 + p3;
                s[j][0] = p0; s[j][1] = p1; s[j][2] = p2; s[j][3] = p3;
            }
        }

        // ---- pack P into PV A-fragments (registers only) ----
        unsigned aph[4][4], apl[4][4];
#pragma unroll
        for (int t = 0; t < 4; t++) {
#pragma unroll
            for (int u = 0; u < 4; u++) {
                int j  = 2*t + ((u & 2) ? 1 : 0);
                int v0 = (u & 1) ? 2 : 0;
                float pa = s[j][v0], pb = s[j][v0 + 1];
                unsigned h = bfpack(pb, pa);
                aph[t][u] = h;
                float ra = pa - __uint_as_float(h << 16);
                float rb = pb - __uint_as_float(h & 0xFFFF0000u);
                apl[t][u] = bfpack(rb, ra);
            }
        }

        // ---- PV: O += P * V (3-term, V via ldmatrix.trans) ----
#pragma unroll
        for (int t = 0; t < 4; t++) {
#pragma unroll
            for (int e = 0; e < 4; e++) {
                unsigned adr = VHIb + lmBase + t*2048 + ((((unsigned)(2*e + laneHi)) ^ (unsigned)kx) << 4);
                unsigned vh[4], vl[4];
                ldm4t(vh, adr);
                ldm4t(vl, adr + 8192);
                mma16(o[2*e],   aph[t], vh[0], vh[1]);
                mma16(o[2*e],   apl[t], vh[0], vh[1]);
                mma16(o[2*e],   aph[t], vl[0], vl[1]);
                mma16(o[2*e+1], aph[t], vh[2], vh[3]);
                mma16(o[2*e+1], apl[t], vh[2], vh[3]);
                mma16(o[2*e+1], aph[t], vl[2], vl[3]);
            }
        }

        // ---- prefetch next tile into the other buffer ----
        if (kt + 1 < nk)
            stage_kv(sb + (unsigned)((kt + 1) & 1) * ABUF,
                     (tokb + (long long)(kt + 1)*64) * HD, tid);
    }

    l0 += __shfl_xor_sync(0xffffffffu, l0, 1);
    l0 += __shfl_xor_sync(0xffffffffu, l0, 2);
    l1 += __shfl_xor_sync(0xffffffffu, l1, 1);
    l1 += __shfl_xor_sync(0xffffffffu, l1, 2);
    float inv0 = 1.0f / l0;
    float inv1 = 1.0f / l1;
    float* out0 = out + (tokb + q0)*HD + 2*r;
    float* out1 = out + (tokb + q1)*HD + 2*r;
#pragma unroll
    for (int j = 0; j < 8; j++) {
        *(float2*)(out0 + 8*j) = make_float2(o[j][0]*inv0, o[j][1]*inv0);
        *(float2*)(out1 + 8*j) = make_float2(o[j][2]*inv1, o[j][3]*inv1);
    }
}

extern "C" void kernel_launch(void* const* d_in, const int* in_sizes, int n_in,
                              void* d_out, int out_size)
{
    const float* x   = (const float*)d_in[0];
    const float* wk1 = (const float*)d_in[1];
    const float* bk1 = (const float*)d_in[2];
    const float* wk2 = (const float*)d_in[3];
    const float* wq1 = (const float*)d_in[4];
    const float* bq1 = (const float*)d_in[5];
    const float* wq2 = (const float*)d_in[6];
    const float* wv1 = (const float*)d_in[7];
    const float* bv1 = (const float*)d_in[8];
    const float* wv2 = (const float*)d_in[9];

    cudaFuncSetAttribute(proj_mma, cudaFuncAttributeMaxDynamicSharedMemorySize, PSM_BYTES);
    cudaFuncSetAttribute(attn_bf16, cudaFuncAttributeMaxDynamicSharedMemorySize, ASM_BYTES);

    conv_w<<<96, 256>>>(wk1, wq1, wv1, wk2, wq2, wv2);
    proj_mma<<<TOK/64, 128, PSM_BYTES>>>(x, bk1, bq1, bv1);
    attn_bf16<<<NBATCH * (SLEN/64), 128, ASM_BYTES>>>((float*)d_out);
}

// round 12
// speedup vs baseline: 1.1575x; 1.1575x over previous
#include <cuda_runtime.h>

#define SLEN 4096
#define NBATCH 8
#define TOK (NBATCH*SLEN)
#define EMB 1024
#define HD 64
#define HALF 32

// Scratch (device globals: allocation-free rule)
__device__ float g_Q[TOK*HD];
// Per-64-key-tile image: [tile][plane 0=Kh 1=Kl 2=Vh 3=Vl][64 keys][128B swizzled row]
__device__ __align__(16) unsigned char g_IMG[(TOK/64) * 32768];
__device__ unsigned short g_W1h[96*1024];   // W1 transposed [n=p*32+h][k], bf16 hi
__device__ unsigned short g_W1l[96*1024];   // lo residual
__device__ unsigned short g_W2h[192*32];    // W2 transposed [p*64+h][j], bf16 hi
__device__ unsigned short g_W2l[192*32];

// ---------- helpers ----------
__device__ __forceinline__ unsigned smem_u32(const void* p) {
    unsigned a;
    asm("{ .reg .u64 t; cvta.to.shared.u64 t, %1; cvt.u32.u64 %0, t; }" : "=r"(a) : "l"(p));
    return a;
}
__device__ __forceinline__ float ex2f(float x) {
    float r;
    asm("ex2.approx.f32 %0, %1;" : "=f"(r) : "f"(x));
    return r;
}
// pack: result.hi = bf16(hi), result.lo = bf16(lo)
__device__ __forceinline__ unsigned bfpack(float hi, float lo) {
    unsigned d;
    asm("cvt.rn.bf16x2.f32 %0, %1, %2;" : "=r"(d) : "f"(hi), "f"(lo));
    return d;
}
// D(16x8,f32) += A(16x16 bf16) * B(16x8 bf16)
__device__ __forceinline__ void mma16(float* c, const unsigned* a, unsigned b0, unsigned b1) {
    asm("mma.sync.aligned.m16n8k16.row.col.f32.bf16.bf16.f32 "
        "{%0,%1,%2,%3}, {%4,%5,%6,%7}, {%8,%9}, {%0,%1,%2,%3};"
        : "+f"(c[0]), "+f"(c[1]), "+f"(c[2]), "+f"(c[3])
        : "r"(a[0]), "r"(a[1]), "r"(a[2]), "r"(a[3]), "r"(b0), "r"(b1));
}
__device__ __forceinline__ void ldm4(unsigned* r, unsigned addr) {
    asm volatile("ldmatrix.sync.aligned.m8n8.x4.shared.b16 {%0,%1,%2,%3}, [%4];"
                 : "=r"(r[0]), "=r"(r[1]), "=r"(r[2]), "=r"(r[3]) : "r"(addr));
}
__device__ __forceinline__ void ldm4t(unsigned* r, unsigned addr) {
    asm volatile("ldmatrix.sync.aligned.m8n8.x4.trans.shared.b16 {%0,%1,%2,%3}, [%4];"
                 : "=r"(r[0]), "=r"(r[1]), "=r"(r[2]), "=r"(r[3]) : "r"(addr));
}
__device__ __forceinline__ void st32(unsigned addr, unsigned v) {
    asm volatile("st.shared.b32 [%0], %1;" :: "r"(addr), "r"(v) : "memory");
}
__device__ __forceinline__ void cpasync16(unsigned saddr, const void* gaddr) {
    asm volatile("cp.async.cg.shared.global [%0], [%1], 16;" :: "r"(saddr), "l"(gaddr) : "memory");
}
__device__ __forceinline__ void cp_commit() { asm volatile("cp.async.commit_group;" ::: "memory"); }
__device__ __forceinline__ void cp_wait0()  { asm volatile("cp.async.wait_group 0;" ::: "memory"); }

// =========================================================================
// conv_w: one-time weight transpose + bf16 hi/lo split.
// =========================================================================
__global__ void conv_w(
    const float* __restrict__ wk1, const float* __restrict__ wq1, const float* __restrict__ wv1,
    const float* __restrict__ wk2, const float* __restrict__ wq2, const float* __restrict__ wv2)
{
    int i = blockIdx.x*blockDim.x + threadIdx.x;
    int stride = gridDim.x*blockDim.x;
    for (int idx = i; idx < 96*1024; idx += stride) {
        int n = idx >> 10, k = idx & 1023;
        int p = n >> 5, h = n & 31;
        const float* w1 = (p == 0) ? wk1 : ((p == 1) ? wq1 : wv1);
        float v = w1[k*HALF + h];
        unsigned hb = bfpack(0.f, v) & 0xFFFFu;
        float res = v - __uint_as_float(hb << 16);
        g_W1h[idx] = (unsigned short)hb;
        g_W1l[idx] = (unsigned short)(bfpack(0.f, res) & 0xFFFFu);
    }
    for (int idx = i; idx < 192*32; idx += stride) {
        int row = idx >> 5, j = idx & 31;
        int p = row >> 6, h = row & 63;
        const float* w2 = (p == 0) ? wk2 : ((p == 1) ? wq2 : wv2);
        float v = w2[j*HD + h];
        unsigned hb = bfpack(0.f, v) & 0xFFFFu;
        float res = v - __uint_as_float(hb << 16);
        g_W2h[idx] = (unsigned short)hb;
        g_W2l[idx] = (unsigned short)(bfpack(0.f, res) & 0xFFFFu);
    }
}

// =========================================================================
// proj_mma (R10 structure; epilogue writes K/V as swizzled bf16 plane image)
// =========================================================================
#define PSM_XH 0
#define PSM_XL 8192
#define PSM_W1H 16384
#define PSM_W1L 28672
#define PSM_W2H 40960
#define PSM_W2L 56320
#define PSM_BYTES 71680

__global__ __launch_bounds__(128, 2) void proj_mma(
    const float* __restrict__ x,
    const float* __restrict__ bk1, const float* __restrict__ bq1, const float* __restrict__ bv1)
{
    extern __shared__ __align__(1024) unsigned char dsm[];
    const unsigned sb = smem_u32(dsm);
    const unsigned XHa = sb + PSM_XH,  XLa = sb + PSM_XL;
    const unsigned W1Ha = sb + PSM_W1H;
    const unsigned W2Ha = sb + PSM_W2H;

    const int tid = threadIdx.x;
    const int w    = tid >> 5;
    const int lane = tid & 31;
    const int g = lane >> 2, r = lane & 3;
    const int laneKey = lane & 15, laneHi = lane >> 4;
    const int tok0 = blockIdx.x * 64;

    // ---- stage W2t once (pitch 80B rows) ----
#pragma unroll
    for (int it = 0; it < 6; it++) {
        int idx = tid + it*128;
        int row = idx >> 2, f = idx & 3;
        *(uint4*)(dsm + PSM_W2H + row*80 + f*16) = *(const uint4*)(g_W2h + row*32 + 8*f);
        *(uint4*)(dsm + PSM_W2L + row*80 + f*16) = *(const uint4*)(g_W2l + row*32 + 8*f);
    }

    float Cf[12][4];
#pragma unroll
    for (int nt = 0; nt < 12; nt++)
#pragma unroll
        for (int u = 0; u < 4; u++) Cf[nt][u] = 0.f;

    for (int s = 0; s < 16; s++) {
        __syncthreads();
        // ---- stage X slab (split to hi/lo bf16, swizzled 128B rows) ----
        {
            const float4* gx = (const float4*)x;
#pragma unroll
            for (int it = 0; it < 8; it++) {
                int idx = tid + it*128;
                int row = idx >> 4, f = idx & 15;
                float4 v = gx[(long long)(tok0 + row)*256 + s*16 + f];
                unsigned h0 = bfpack(v.y, v.x);
                float r0 = v.x - __uint_as_float(h0 << 16);
                float r1 = v.y - __uint_as_float(h0 & 0xFFFF0000u);
                unsigned l0 = bfpack(r1, r0);
                unsigned h1 = bfpack(v.w, v.z);
                float r2 = v.z - __uint_as_float(h1 << 16);
                float r3 = v.w - __uint_as_float(h1 & 0xFFFF0000u);
                unsigned l1 = bfpack(r3, r2);
                unsigned off = row*128 + ((((unsigned)(f >> 1)) ^ (unsigned)(row & 7)) << 4) + (f & 1)*8;
                st32(XHa + off, h0); st32(XHa + off + 4, h1);
                st32(XLa + off, l0); st32(XLa + off + 4, l1);
            }
        }
        // ---- stage W1t slab ----
#pragma unroll
        for (int it = 0; it < 6; it++) {
            int idx = tid + it*128;
            int row = idx >> 3, f = idx & 7;
            unsigned off = row*128 + (((unsigned)f ^ (unsigned)(row & 7)) << 4);
            *(uint4*)(dsm + PSM_W1H + off) = *(const uint4*)(g_W1h + row*1024 + s*64 + 8*f);
            *(uint4*)(dsm + PSM_W1L + off) = *(const uint4*)(g_W1l + row*1024 + s*64 + 8*f);
        }
        __syncthreads();

        // ---- GEMM1: Cf += X * W1t (3-term bf16 split) ----
#pragma unroll
        for (int c = 0; c < 4; c++) {
            unsigned axh[4], axl[4];
            unsigned adrA = XHa + (16*w + laneKey)*128
                          + ((((unsigned)(2*c + laneHi)) ^ (unsigned)(laneKey & 7)) << 4);
            ldm4(axh, adrA);
            ldm4(axl, adrA + (PSM_XL - PSM_XH));
#pragma unroll
            for (int tp = 0; tp < 6; tp++) {
                unsigned adrB = W1Ha + (16*tp + laneKey)*128
                              + ((((unsigned)(2*c + laneHi)) ^ (unsigned)(laneKey & 7)) << 4);
                unsigned bh[4], bl[4];
                ldm4(bh, adrB);
                ldm4(bl, adrB + (PSM_W1L - PSM_W1H));
                mma16(Cf[2*tp],   axh, bh[0], bh[2]);
                mma16(Cf[2*tp],   axl, bh[0], bh[2]);
                mma16(Cf[2*tp],   axh, bl[0], bl[2]);
                mma16(Cf[2*tp+1], axh, bh[1], bh[3]);
                mma16(Cf[2*tp+1], axl, bh[1], bh[3]);
                mma16(Cf[2*tp+1], axh, bl[1], bl[3]);
            }
        }
    }

    // ---- bias + tanh in registers ----
#pragma unroll
    for (int nt = 0; nt < 12; nt++) {
        int p = nt >> 2;
        int h0 = (nt & 3)*8 + 2*r;
        const float* b1 = (p == 0) ? bk1 : ((p == 1) ? bq1 : bv1);
        float bb0 = b1[h0], bb1 = b1[h0 + 1];
        Cf[nt][0] = tanhf(Cf[nt][0] + bb0);
        Cf[nt][1] = tanhf(Cf[nt][1] + bb1);
        Cf[nt][2] = tanhf(Cf[nt][2] + bb0);
        Cf[nt][3] = tanhf(Cf[nt][3] + bb1);
    }

    // ---- GEMM2 + epilogue ----
    const int key0 = 16*w + g;                       // local key/token row in tile
    unsigned char* img = g_IMG + (long long)(tok0 >> 6) * 32768;
#pragma unroll
    for (int p = 0; p < 3; p++) {
        float o2[8][4];
#pragma unroll
        for (int e = 0; e < 8; e++)
#pragma unroll
            for (int u = 0; u < 4; u++) o2[e][u] = 0.f;

#pragma unroll
        for (int kc = 0; kc < 2; kc++) {
            int nt0 = 4*p + 2*kc;
            unsigned ah[4], al[4];
#pragma unroll
            for (int u = 0; u < 4; u++) {
                int nt = nt0 + ((u & 2) ? 1 : 0);
                int v0 = (u & 1) ? 2 : 0;
                float pa = Cf[nt][v0], pb = Cf[nt][v0 + 1];
                unsigned hh = bfpack(pb, pa);
                ah[u] = hh;
                float ra = pa - __uint_as_float(hh << 16);
                float rb = pb - __uint_as_float(hh & 0xFFFF0000u);
                al[u] = bfpack(rb, ra);
            }
#pragma unroll
            for (int e2 = 0; e2 < 4; e2++) {
                unsigned adr = W2Ha + (p*64 + 16*e2 + laneKey)*80 + kc*32 + laneHi*16;
                unsigned bh[4], bl[4];
                ldm4(bh, adr);
                ldm4(bl, adr + (PSM_W2L - PSM_W2H));
                mma16(o2[2*e2],   ah, bh[0], bh[2]);
                mma16(o2[2*e2],   al, bh[0], bh[2]);
                mma16(o2[2*e2],   ah, bl[0], bl[2]);
                mma16(o2[2*e2+1], ah, bh[1], bh[3]);
                mma16(o2[2*e2+1], al, bh[1], bh[3]);
                mma16(o2[2*e2+1], ah, bl[1], bl[3]);
            }
        }

        if (p == 1) {            // Q stays fp32
            long long row0 = tok0 + key0;
#pragma unroll
            for (int e = 0; e < 8; e++) {
                int h0 = 8*e + 2*r;
                *(float2*)&g_Q[row0*HD + h0]       = make_float2(o2[e][0], o2[e][1]);
                *(float2*)&g_Q[(row0 + 8)*HD + h0] = make_float2(o2[e][2], o2[e][3]);
            }
        } else {                 // K -> planes 0/1, V -> planes 2/3 (swizzled image)
            unsigned char* ph = img + ((p == 0) ? 0 : 16384);
            int sw = (key0 & 7) << 4;    // (key0+8)&7 == key0&7
#pragma unroll
            for (int e = 0; e < 8; e++) {
                unsigned inn0 = key0*128       + (((unsigned)(e << 4)) ^ (unsigned)sw) + r*4;
                unsigned inn1 = (key0+8)*128   + (((unsigned)(e << 4)) ^ (unsigned)sw) + r*4;
                unsigned h0w = bfpack(o2[e][1], o2[e][0]);
                float ra = o2[e][0] - __uint_as_float(h0w << 16);
                float rb = o2[e][1] - __uint_as_float(h0w & 0xFFFF0000u);
                unsigned l0w = bfpack(rb, ra);
                unsigned h1w = bfpack(o2[e][3], o2[e][2]);
                float rc = o2[e][2] - __uint_as_float(h1w << 16);
                float rd = o2[e][3] - __uint_as_float(h1w & 0xFFFF0000u);
                unsigned l1w = bfpack(rd, rc);
                *(unsigned*)(ph + inn0)        = h0w;
                *(unsigned*)(ph + 8192 + inn0) = l0w;
                *(unsigned*)(ph + inn1)        = h1w;
                *(unsigned*)(ph + 8192 + inn1) = l1w;
            }
        }
    }
}

// =========================================================================
// attn_bf16 v3: cp.async double-buffered tile pipeline (pure 32KB copies).
// =========================================================================
#define ABUF 32768
#define ASM_BYTES 65536

__global__ __launch_bounds__(128, 3) void attn_bf16(float* __restrict__ out)
{
    extern __shared__ __align__(1024) unsigned char asm_[];
    const unsigned sb = smem_u32(asm_);

    const int tid  = threadIdx.x;
    const int w    = tid >> 5;
    const int lane = tid & 31;
    const int g    = lane >> 2;
    const int r    = lane & 3;
    const int laneKey = lane & 15;
    const int laneHi  = lane >> 4;
    const int kx      = laneKey & 7;
    const unsigned lmBase = laneKey * 128;

    const int bid = blockIdx.x;
    const int b   = bid & 7;
    const int qt  = 63 - (bid >> 3);
    const int nk  = qt + 1;
    const long long tokb = (long long)b*SLEN;
    const long long qrow0 = tokb + (long long)qt*64;
    const int q0 = qt*64 + 16*w + g;
    const int q1 = q0 + 8;

    // ---- prime: async-copy tile 0 into buffer 0 ----
    {
        const unsigned char* src = g_IMG + (long long)(b*64) * 32768;
#pragma unroll
        for (int it = 0; it < 16; it++) {
            unsigned idx = (unsigned)(tid + it*128) * 16u;
            cpasync16(sb + idx, src + idx);
        }
        cp_commit();
    }

    // ---- Q fragments (hi/lo bf16), prescaled by 0.125*log2(e) ----
    const float SC = 0.1803368801111204f;
    unsigned qhi[4][4], qlo[4][4];
    {
        const float* qA = g_Q + (qrow0 + 16*w + g)*HD;
        const float* qB = qA + 8*HD;
#pragma unroll
        for (int c = 0; c < 4; c++) {
#pragma unroll
            for (int u = 0; u < 4; u++) {
                const float* src = (u & 1) ? qB : qA;
                int d = 16*c + 2*r + ((u & 2) ? 8 : 0);
                float2 xv = *(const float2*)(src + d);
                float v0 = xv.x * SC, v1 = xv.y * SC;
                unsigned h = bfpack(v1, v0);
                qhi[c][u] = h;
                float r0 = v0 - __uint_as_float(h << 16);
                float r1 = v1 - __uint_as_float(h & 0xFFFF0000u);
                qlo[c][u] = bfpack(r1, r0);
            }
        }
    }

    float o[8][4];
#pragma unroll
    for (int j = 0; j < 8; j++)
#pragma unroll
        for (int u = 0; u < 4; u++) o[j][u] = 0.f;
    float l0 = 0.f, l1 = 0.f;

    for (int kt = 0; kt < nk; kt++) {
        cp_wait0();
        __syncthreads();                      // tile kt resident for all threads
        const unsigned cur = sb + (unsigned)(kt & 1) * ABUF;
        const unsigned KHIb = cur, VHIb = cur + 16384;

        // ---- issue next tile's async copy into the other buffer ----
        if (kt + 1 < nk) {
            const unsigned char* src = g_IMG + (long long)(b*64 + kt + 1) * 32768;
            unsigned dst = sb + (unsigned)((kt + 1) & 1) * ABUF;
#pragma unroll
            for (int it = 0; it < 16; it++) {
                unsigned idx = (unsigned)(tid + it*128) * 16u;
                cpasync16(dst + idx, src + idx);
            }
            cp_commit();
        }

        // ---- QK: S[16 x 64] via 3-term bf16 split ----
        float s[8][4];
#pragma unroll
        for (int j = 0; j < 8; j++)
#pragma unroll
            for (int u = 0; u < 4; u++) s[j][u] = 0.f;

#pragma unroll
        for (int c = 0; c < 4; c++) {
#pragma unroll
            for (int t = 0; t < 4; t++) {
                unsigned adr = KHIb + lmBase + t*2048 + ((((unsigned)(2*c + laneHi)) ^ (unsigned)kx) << 4);
                unsigned kh[4], kl[4];
                ldm4(kh, adr);
                ldm4(kl, adr + 8192);
                mma16(s[2*t],   qhi[c], kh[0], kh[2]);
                mma16(s[2*t],   qlo[c], kh[0], kh[2]);
                mma16(s[2*t],   qhi[c], kl[0], kl[2]);
                mma16(s[2*t+1], qhi[c], kh[1], kh[3]);
                mma16(s[2*t+1], qlo[c], kh[1], kh[3]);
                mma16(s[2*t+1], qhi[c], kl[1], kl[3]);
            }
        }

        // ---- softmax (p = 2^s, no-max) + causal mask ----
        const int kb = kt*64;
        if (kt == qt) {
#pragma unroll
            for (int j = 0; j < 8; j++) {
                int k0 = kb + 8*j + 2*r;
                float p0 = (k0     > q0) ? 0.f : ex2f(fminf(s[j][0], 80.f));
                float p1 = (k0 + 1 > q0) ? 0.f : ex2f(fminf(s[j][1], 80.f));
                float p2 = (k0     > q1) ? 0.f : ex2f(fminf(s[j][2], 80.f));
                float p3 = (k0 + 1 > q1) ? 0.f : ex2f(fminf(s[j][3], 80.f));
                l0 += p0 + p1; l1 += p2 + p3;
                s[j][0] = p0; s[j][1] = p1; s[j][2] = p2; s[j][3] = p3;
            }
        } else {
#pragma unroll
            for (int j = 0; j < 8; j++) {
                float p0 = ex2f(fminf(s[j][0], 80.f));
                float p1 = ex2f(fminf(s[j][1], 80.f));
                float p2 = ex2f(fminf(s[j][2], 80.f));
                float p3 = ex2f(fminf(s[j][3], 80.f));
                l0 += p0 + p1; l1 += p2 + p3;
                s[j][0] = p0; s[j][1] = p1; s[j][2] = p2; s[j][3] = p3;
            }
        }

        // ---- pack P into PV A-fragments (registers only) ----
        unsigned aph[4][4], apl[4][4];
#pragma unroll
        for (int t = 0; t < 4; t++) {
#pragma unroll
            for (int u = 0; u < 4; u++) {
                int j  = 2*t + ((u & 2) ? 1 : 0);
                int v0 = (u & 1) ? 2 : 0;
                float pa = s[j][v0], pb = s[j][v0 + 1];
                unsigned h = bfpack(pb, pa);
                aph[t][u] = h;
                float ra = pa - __uint_as_float(h << 16);
                float rb = pb - __uint_as_float(h & 0xFFFF0000u);
                apl[t][u] = bfpack(rb, ra);
            }
        }

        // ---- PV: O += P * V (3-term, V via ldmatrix.trans) ----
#pragma unroll
        for (int t = 0; t < 4; t++) {
#pragma unroll
            for (int e = 0; e < 4; e++) {
                unsigned adr = VHIb + lmBase + t*2048 + ((((unsigned)(2*e + laneHi)) ^ (unsigned)kx) << 4);
                unsigned vh[4], vl[4];
                ldm4t(vh, adr);
                ldm4t(vl, adr + 8192);
                mma16(o[2*e],   aph[t], vh[0], vh[1]);
                mma16(o[2*e],   apl[t], vh[0], vh[1]);
                mma16(o[2*e],   aph[t], vl[0], vl[1]);
                mma16(o[2*e+1], aph[t], vh[2], vh[3]);
                mma16(o[2*e+1], apl[t], vh[2], vh[3]);
                mma16(o[2*e+1], aph[t], vl[2], vl[3]);
            }
        }
        __syncthreads();   // all warps done with buf[kt&1] before its next overwrite
    }

    l0 += __shfl_xor_sync(0xffffffffu, l0, 1);
    l0 += __shfl_xor_sync(0xffffffffu, l0, 2);
    l1 += __shfl_xor_sync(0xffffffffu, l1, 1);
    l1 += __shfl_xor_sync(0xffffffffu, l1, 2);
    float inv0 = 1.0f / l0;
    float inv1 = 1.0f / l1;
    float* out0 = out + (tokb + q0)*HD + 2*r;
    float* out1 = out + (tokb + q1)*HD + 2*r;
#pragma unroll
    for (int j = 0; j < 8; j++) {
        *(float2*)(out0 + 8*j) = make_float2(o[j][0]*inv0, o[j][1]*inv0);
        *(float2*)(out1 + 8*j) = make_float2(o[j][2]*inv1, o[j][3]*inv1);
    }
}

extern "C" void kernel_launch(void* const* d_in, const int* in_sizes, int n_in,
                              void* d_out, int out_size)
{
    const float* x   = (const float*)d_in[0];
    const float* wk1 = (const float*)d_in[1];
    const float* bk1 = (const float*)d_in[2];
    const float* wk2 = (const float*)d_in[3];
    const float* wq1 = (const float*)d_in[4];
    const float* bq1 = (const float*)d_in[5];
    const float* wq2 = (const float*)d_in[6];
    const float* wv1 = (const float*)d_in[7];
    const float* bv1 = (const float*)d_in[8];
    const float* wv2 = (const float*)d_in[9];

    cudaFuncSetAttribute(proj_mma, cudaFuncAttributeMaxDynamicSharedMemorySize, PSM_BYTES);
    cudaFuncSetAttribute(attn_bf16, cudaFuncAttributeMaxDynamicSharedMemorySize, ASM_BYTES);

    conv_w<<<96, 256>>>(wk1, wq1, wv1, wk2, wq2, wv2);
    proj_mma<<<TOK/64, 128, PSM_BYTES>>>(x, bk1, bq1, bv1);
    attn_bf16<<<NBATCH * (SLEN/64), 128, ASM_BYTES>>>((float*)d_out);
}

// round 13
// speedup vs baseline: 1.2763x; 1.1026x over previous
#include <cuda_runtime.h>

#define SLEN 4096
#define NBATCH 8
#define TOK (NBATCH*SLEN)
#define EMB 1024
#define HD 64
#define HALF 32

#define TILES_PER_B 2080            // 64*65/2
#define TOTAL_TILES (NBATCH*TILES_PER_B)
#define NCTA 444                    // 148 SMs x 3 CTAs
#define UNIT 38                     // ceil(16640/444)

// Scratch (device globals: allocation-free rule; zero-initialized at load)
__device__ float g_Q[TOK*HD];
__device__ float g_O[TOK*HD];       // split-K fp32 accumulator
__device__ float g_L[TOK];          // split-K softmax denominators
// Per-64-key-tile image: [tile][plane 0=Kh 1=Kl 2=Vh 3=Vl][64 keys][128B swizzled row]
__device__ __align__(16) unsigned char g_IMG[(TOK/64) * 32768];
__device__ unsigned short g_W1h[96*1024];
__device__ unsigned short g_W1l[96*1024];
__device__ unsigned short g_W2h[192*32];
__device__ unsigned short g_W2l[192*32];

// ---------- helpers ----------
__device__ __forceinline__ unsigned smem_u32(const void* p) {
    unsigned a;
    asm("{ .reg .u64 t; cvta.to.shared.u64 t, %1; cvt.u32.u64 %0, t; }" : "=r"(a) : "l"(p));
    return a;
}
__device__ __forceinline__ float ex2f(float x) {
    float r;
    asm("ex2.approx.f32 %0, %1;" : "=f"(r) : "f"(x));
    return r;
}
__device__ __forceinline__ unsigned bfpack(float hi, float lo) {
    unsigned d;
    asm("cvt.rn.bf16x2.f32 %0, %1, %2;" : "=r"(d) : "f"(hi), "f"(lo));
    return d;
}
__device__ __forceinline__ void mma16(float* c, const unsigned* a, unsigned b0, unsigned b1) {
    asm("mma.sync.aligned.m16n8k16.row.col.f32.bf16.bf16.f32 "
        "{%0,%1,%2,%3}, {%4,%5,%6,%7}, {%8,%9}, {%0,%1,%2,%3};"
        : "+f"(c[0]), "+f"(c[1]), "+f"(c[2]), "+f"(c[3])
        : "r"(a[0]), "r"(a[1]), "r"(a[2]), "r"(a[3]), "r"(b0), "r"(b1));
}
__device__ __forceinline__ void ldm4(unsigned* r, unsigned addr) {
    asm volatile("ldmatrix.sync.aligned.m8n8.x4.shared.b16 {%0,%1,%2,%3}, [%4];"
                 : "=r"(r[0]), "=r"(r[1]), "=r"(r[2]), "=r"(r[3]) : "r"(addr));
}
__device__ __forceinline__ void ldm4t(unsigned* r, unsigned addr) {
    asm volatile("ldmatrix.sync.aligned.m8n8.x4.trans.shared.b16 {%0,%1,%2,%3}, [%4];"
                 : "=r"(r[0]), "=r"(r[1]), "=r"(r[2]), "=r"(r[3]) : "r"(addr));
}
__device__ __forceinline__ void st32(unsigned addr, unsigned v) {
    asm volatile("st.shared.b32 [%0], %1;" :: "r"(addr), "r"(v) : "memory");
}
__device__ __forceinline__ void cpasync16(unsigned saddr, const void* gaddr) {
    asm volatile("cp.async.cg.shared.global [%0], [%1], 16;" :: "r"(saddr), "l"(gaddr) : "memory");
}
__device__ __forceinline__ void cp_commit() { asm volatile("cp.async.commit_group;" ::: "memory"); }
__device__ __forceinline__ void cp_wait0()  { asm volatile("cp.async.wait_group 0;" ::: "memory"); }

// =========================================================================
// conv_w: one-time weight transpose + bf16 hi/lo split.
// =========================================================================
__global__ void conv_w(
    const float* __restrict__ wk1, const float* __restrict__ wq1, const float* __restrict__ wv1,
    const float* __restrict__ wk2, const float* __restrict__ wq2, const float* __restrict__ wv2)
{
    int i = blockIdx.x*blockDim.x + threadIdx.x;
    int stride = gridDim.x*blockDim.x;
    for (int idx = i; idx < 96*1024; idx += stride) {
        int n = idx >> 10, k = idx & 1023;
        int p = n >> 5, h = n & 31;
        const float* w1 = (p == 0) ? wk1 : ((p == 1) ? wq1 : wv1);
        float v = w1[k*HALF + h];
        unsigned hb = bfpack(0.f, v) & 0xFFFFu;
        float res = v - __uint_as_float(hb << 16);
        g_W1h[idx] = (unsigned short)hb;
        g_W1l[idx] = (unsigned short)(bfpack(0.f, res) & 0xFFFFu);
    }
    for (int idx = i; idx < 192*32; idx += stride) {
        int row = idx >> 5, j = idx & 31;
        int p = row >> 6, h = row & 63;
        const float* w2 = (p == 0) ? wk2 : ((p == 1) ? wq2 : wv2);
        float v = w2[j*HD + h];
        unsigned hb = bfpack(0.f, v) & 0xFFFFu;
        float res = v - __uint_as_float(hb << 16);
        g_W2h[idx] = (unsigned short)hb;
        g_W2l[idx] = (unsigned short)(bfpack(0.f, res) & 0xFFFFu);
    }
}

// =========================================================================
// proj_mma (unchanged from R12 — writes Q fp32 + K/V swizzled bf16 image)
// =========================================================================
#define PSM_XH 0
#define PSM_XL 8192
#define PSM_W1H 16384
#define PSM_W1L 28672
#define PSM_W2H 40960
#define PSM_W2L 56320
#define PSM_BYTES 71680

__global__ __launch_bounds__(128, 2) void proj_mma(
    const float* __restrict__ x,
    const float* __restrict__ bk1, const float* __restrict__ bq1, const float* __restrict__ bv1)
{
    extern __shared__ __align__(1024) unsigned char dsm[];
    const unsigned sb = smem_u32(dsm);
    const unsigned XHa = sb + PSM_XH,  XLa = sb + PSM_XL;
    const unsigned W1Ha = sb + PSM_W1H;
    const unsigned W2Ha = sb + PSM_W2H;

    const int tid = threadIdx.x;
    const int w    = tid >> 5;
    const int lane = tid & 31;
    const int g = lane >> 2, r = lane & 3;
    const int laneKey = lane & 15, laneHi = lane >> 4;
    const int tok0 = blockIdx.x * 64;

#pragma unroll
    for (int it = 0; it < 6; it++) {
        int idx = tid + it*128;
        int row = idx >> 2, f = idx & 3;
        *(uint4*)(dsm + PSM_W2H + row*80 + f*16) = *(const uint4*)(g_W2h + row*32 + 8*f);
        *(uint4*)(dsm + PSM_W2L + row*80 + f*16) = *(const uint4*)(g_W2l + row*32 + 8*f);
    }

    float Cf[12][4];
#pragma unroll
    for (int nt = 0; nt < 12; nt++)
#pragma unroll
        for (int u = 0; u < 4; u++) Cf[nt][u] = 0.f;

    for (int s = 0; s < 16; s++) {
        __syncthreads();
        {
            const float4* gx = (const float4*)x;
#pragma unroll
            for (int it = 0; it < 8; it++) {
                int idx = tid + it*128;
                int row = idx >> 4, f = idx & 15;
                float4 v = gx[(long long)(tok0 + row)*256 + s*16 + f];
                unsigned h0 = bfpack(v.y, v.x);
                float r0 = v.x - __uint_as_float(h0 << 16);
                float r1 = v.y - __uint_as_float(h0 & 0xFFFF0000u);
                unsigned l0 = bfpack(r1, r0);
                unsigned h1 = bfpack(v.w, v.z);
                float r2 = v.z - __uint_as_float(h1 << 16);
                float r3 = v.w - __uint_as_float(h1 & 0xFFFF0000u);
                unsigned l1 = bfpack(r3, r2);
                unsigned off = row*128 + ((((unsigned)(f >> 1)) ^ (unsigned)(row & 7)) << 4) + (f & 1)*8;
                st32(XHa + off, h0); st32(XHa + off + 4, h1);
                st32(XLa + off, l0); st32(XLa + off + 4, l1);
            }
        }
#pragma unroll
        for (int it = 0; it < 6; it++) {
            int idx = tid + it*128;
            int row = idx >> 3, f = idx & 7;
            unsigned off = row*128 + (((unsigned)f ^ (unsigned)(row & 7)) << 4);
            *(uint4*)(dsm + PSM_W1H + off) = *(const uint4*)(g_W1h + row*1024 + s*64 + 8*f);
            *(uint4*)(dsm + PSM_W1L + off) = *(const uint4*)(g_W1l + row*1024 + s*64 + 8*f);
        }
        __syncthreads();

#pragma unroll
        for (int c = 0; c < 4; c++) {
            unsigned axh[4], axl[4];
            unsigned adrA = XHa + (16*w + laneKey)*128
                          + ((((unsigned)(2*c + laneHi)) ^ (unsigned)(laneKey & 7)) << 4);
            ldm4(axh, adrA);
            ldm4(axl, adrA + (PSM_XL - PSM_XH));
#pragma unroll
            for (int tp = 0; tp < 6; tp++) {
                unsigned adrB = W1Ha + (16*tp + laneKey)*128
                              + ((((unsigned)(2*c + laneHi)) ^ (unsigned)(laneKey & 7)) << 4);
                unsigned bh[4], bl[4];
                ldm4(bh, adrB);
                ldm4(bl, adrB + (PSM_W1L - PSM_W1H));
                mma16(Cf[2*tp],   axh, bh[0], bh[2]);
                mma16(Cf[2*tp],   axl, bh[0], bh[2]);
                mma16(Cf[2*tp],   axh, bl[0], bl[2]);
                mma16(Cf[2*tp+1], axh, bh[1], bh[3]);
                mma16(Cf[2*tp+1], axl, bh[1], bh[3]);
                mma16(Cf[2*tp+1], axh, bl[1], bl[3]);
            }
        }
    }

#pragma unroll
    for (int nt = 0; nt < 12; nt++) {
        int p = nt >> 2;
        int h0 = (nt & 3)*8 + 2*r;
        const float* b1 = (p == 0) ? bk1 : ((p == 1) ? bq1 : bv1);
        float bb0 = b1[h0], bb1 = b1[h0 + 1];
        Cf[nt][0] = tanhf(Cf[nt][0] + bb0);
        Cf[nt][1] = tanhf(Cf[nt][1] + bb1);
        Cf[nt][2] = tanhf(Cf[nt][2] + bb0);
        Cf[nt][3] = tanhf(Cf[nt][3] + bb1);
    }

    const int key0 = 16*w + g;
    unsigned char* img = g_IMG + (long long)(tok0 >> 6) * 32768;
#pragma unroll
    for (int p = 0; p < 3; p++) {
        float o2[8][4];
#pragma unroll
        for (int e = 0; e < 8; e++)
#pragma unroll
            for (int u = 0; u < 4; u++) o2[e][u] = 0.f;

#pragma unroll
        for (int kc = 0; kc < 2; kc++) {
            int nt0 = 4*p + 2*kc;
            unsigned ah[4], al[4];
#pragma unroll
            for (int u = 0; u < 4; u++) {
                int nt = nt0 + ((u & 2) ? 1 : 0);
                int v0 = (u & 1) ? 2 : 0;
                float pa = Cf[nt][v0], pb = Cf[nt][v0 + 1];
                unsigned hh = bfpack(pb, pa);
                ah[u] = hh;
                float ra = pa - __uint_as_float(hh << 16);
                float rb = pb - __uint_as_float(hh & 0xFFFF0000u);
                al[u] = bfpack(rb, ra);
            }
#pragma unroll
            for (int e2 = 0; e2 < 4; e2++) {
                unsigned adr = W2Ha + (p*64 + 16*e2 + laneKey)*80 + kc*32 + laneHi*16;
                unsigned bh[4], bl[4];
                ldm4(bh, adr);
                ldm4(bl, adr + (PSM_W2L - PSM_W2H));
                mma16(o2[2*e2],   ah, bh[0], bh[2]);
                mma16(o2[2*e2],   al, bh[0], bh[2]);
                mma16(o2[2*e2],   ah, bl[0], bl[2]);
                mma16(o2[2*e2+1], ah, bh[1], bh[3]);
                mma16(o2[2*e2+1], al, bh[1], bh[3]);
                mma16(o2[2*e2+1], ah, bl[1], bl[3]);
            }
        }

        if (p == 1) {
            long long row0 = tok0 + key0;
#pragma unroll
            for (int e = 0; e < 8; e++) {
                int h0 = 8*e + 2*r;
                *(float2*)&g_Q[row0*HD + h0]       = make_float2(o2[e][0], o2[e][1]);
                *(float2*)&g_Q[(row0 + 8)*HD + h0] = make_float2(o2[e][2], o2[e][3]);
            }
        } else {
            unsigned char* ph = img + ((p == 0) ? 0 : 16384);
            int sw = (key0 & 7) << 4;
#pragma unroll
            for (int e = 0; e < 8; e++) {
                unsigned inn0 = key0*128       + (((unsigned)(e << 4)) ^ (unsigned)sw) + r*4;
                unsigned inn1 = (key0+8)*128   + (((unsigned)(e << 4)) ^ (unsigned)sw) + r*4;
                unsigned h0w = bfpack(o2[e][1], o2[e][0]);
                float ra = o2[e][0] - __uint_as_float(h0w << 16);
                float rb = o2[e][1] - __uint_as_float(h0w & 0xFFFF0000u);
                unsigned l0w = bfpack(rb, ra);
                unsigned h1w = bfpack(o2[e][3], o2[e][2]);
                float rc = o2[e][2] - __uint_as_float(h1w << 16);
                float rd = o2[e][3] - __uint_as_float(h1w & 0xFFFF0000u);
                unsigned l1w = bfpack(rd, rc);
                *(unsigned*)(ph + inn0)        = h0w;
                *(unsigned*)(ph + 8192 + inn0) = l0w;
                *(unsigned*)(ph + inn1)        = h1w;
                *(unsigned*)(ph + 8192 + inn1) = l1w;
            }
        }
    }
}

// =========================================================================
// attn_bf16 v4: balanced split-K. 444 CTAs x 38 flat tiles each.
//   No-max softmax => partials merge by pure addition into g_O/g_L.
// =========================================================================
#define ABUF 32768
#define ASM_BYTES 65536

__global__ __launch_bounds__(128, 3) void attn_split()
{
    extern __shared__ __align__(1024) unsigned char asm_[];
    const unsigned sb = smem_u32(asm_);

    const int tid  = threadIdx.x;
    const int w    = tid >> 5;
    const int lane = tid & 31;
    const int g    = lane >> 2;
    const int r    = lane & 3;
    const int laneKey = lane & 15;
    const int laneHi  = lane >> 4;
    const int kx      = laneKey & 7;
    const unsigned lmBase = laneKey * 128;
    const float SC = 0.1803368801111204f;    // 1/sqrt(64) * log2(e)

    int t  = blockIdx.x * UNIT;
    int t1 = t + UNIT; if (t1 > TOTAL_TILES) t1 = TOTAL_TILES;

    while (t < t1) {
        // ---- decode (b, qt, kt0) from flat tile index ----
        int b  = t / TILES_PER_B;
        int rr = t - b*TILES_PER_B;
        int qt = (int)((sqrtf(8.f*(float)rr + 1.f) - 1.f) * 0.5f);
        while ((qt+1)*(qt+2)/2 <= rr) qt++;
        while (qt*(qt+1)/2 > rr) qt--;
        int kt0 = rr - qt*(qt+1)/2;
        int ntl = qt + 1 - kt0;
        if (ntl > t1 - t) ntl = t1 - t;

        const long long tokb = (long long)b*SLEN;
        const int q0 = qt*64 + 16*w + g;
        const int q1 = q0 + 8;

        // ---- prime tile kt0 ----
        {
            const unsigned char* src = g_IMG + (long long)(b*64 + kt0) * 32768;
#pragma unroll
            for (int it = 0; it < 16; it++) {
                unsigned idx = (unsigned)(tid + it*128) * 16u;
                cpasync16(sb + idx, src + idx);
            }
            cp_commit();
        }

        // ---- Q fragments for (b, qt) ----
        unsigned qhi[4][4], qlo[4][4];
        {
            const float* qA = g_Q + (tokb + q0)*HD;
            const float* qB = qA + 8*HD;
#pragma unroll
            for (int c = 0; c < 4; c++) {
#pragma unroll
                for (int u = 0; u < 4; u++) {
                    const float* src = (u & 1) ? qB : qA;
                    int d = 16*c + 2*r + ((u & 2) ? 8 : 0);
                    float2 xv = *(const float2*)(src + d);
                    float v0 = xv.x * SC, v1 = xv.y * SC;
                    unsigned h = bfpack(v1, v0);
                    qhi[c][u] = h;
                    float r0 = v0 - __uint_as_float(h << 16);
                    float r1 = v1 - __uint_as_float(h & 0xFFFF0000u);
                    qlo[c][u] = bfpack(r1, r0);
                }
            }
        }

        float o[8][4];
#pragma unroll
        for (int j = 0; j < 8; j++)
#pragma unroll
            for (int u = 0; u < 4; u++) o[j][u] = 0.f;
        float l0 = 0.f, l1 = 0.f;

        for (int i = 0; i < ntl; i++) {
            const int kt = kt0 + i;
            cp_wait0();
            __syncthreads();
            const unsigned cur = sb + (unsigned)(i & 1) * ABUF;
            const unsigned KHIb = cur, VHIb = cur + 16384;

            if (i + 1 < ntl) {
                const unsigned char* src = g_IMG + (long long)(b*64 + kt + 1) * 32768;
                unsigned dst = sb + (unsigned)((i + 1) & 1) * ABUF;
#pragma unroll
                for (int it = 0; it < 16; it++) {
                    unsigned idx = (unsigned)(tid + it*128) * 16u;
                    cpasync16(dst + idx, src + idx);
                }
                cp_commit();
            }

            // ---- QK ----
            float s[8][4];
#pragma unroll
            for (int j = 0; j < 8; j++)
#pragma unroll
                for (int u = 0; u < 4; u++) s[j][u] = 0.f;

#pragma unroll
            for (int c = 0; c < 4; c++) {
#pragma unroll
                for (int tt = 0; tt < 4; tt++) {
                    unsigned adr = KHIb + lmBase + tt*2048 + ((((unsigned)(2*c + laneHi)) ^ (unsigned)kx) << 4);
                    unsigned kh[4], kl[4];
                    ldm4(kh, adr);
                    ldm4(kl, adr + 8192);
                    mma16(s[2*tt],   qhi[c], kh[0], kh[2]);
                    mma16(s[2*tt],   qlo[c], kh[0], kh[2]);
                    mma16(s[2*tt],   qhi[c], kl[0], kl[2]);
                    mma16(s[2*tt+1], qhi[c], kh[1], kh[3]);
                    mma16(s[2*tt+1], qlo[c], kh[1], kh[3]);
                    mma16(s[2*tt+1], qhi[c], kl[1], kl[3]);
                }
            }

            // ---- softmax (p = 2^s, no-max) + causal mask ----
            const int kb = kt*64;
            if (kt == qt) {
#pragma unroll
                for (int j = 0; j < 8; j++) {
                    int k0 = kb + 8*j + 2*r;
                    float p0 = (k0     > q0) ? 0.f : ex2f(fminf(s[j][0], 80.f));
                    float p1 = (k0 + 1 > q0) ? 0.f : ex2f(fminf(s[j][1], 80.f));
                    float p2 = (k0     > q1) ? 0.f : ex2f(fminf(s[j][2], 80.f));
                    float p3 = (k0 + 1 > q1) ? 0.f : ex2f(fminf(s[j][3], 80.f));
                    l0 += p0 + p1; l1 += p2 + p3;
                    s[j][0] = p0; s[j][1] = p1; s[j][2] = p2; s[j][3] = p3;
                }
            } else {
#pragma unroll
                for (int j = 0; j < 8; j++) {
                    float p0 = ex2f(fminf(s[j][0], 80.f));
                    float p1 = ex2f(fminf(s[j][1], 80.f));
                    float p2 = ex2f(fminf(s[j][2], 80.f));
                    float p3 = ex2f(fminf(s[j][3], 80.f));
                    l0 += p0 + p1; l1 += p2 + p3;
                    s[j][0] = p0; s[j][1] = p1; s[j][2] = p2; s[j][3] = p3;
                }
            }

            // ---- pack P (registers only) ----
            unsigned aph[4][4], apl[4][4];
#pragma unroll
            for (int tt = 0; tt < 4; tt++) {
#pragma unroll
                for (int u = 0; u < 4; u++) {
                    int j  = 2*tt + ((u & 2) ? 1 : 0);
                    int v0 = (u & 1) ? 2 : 0;
                    float pa = s[j][v0], pb = s[j][v0 + 1];
                    unsigned h = bfpack(pb, pa);
                    aph[tt][u] = h;
                    float ra = pa - __uint_as_float(h << 16);
                    float rb = pb - __uint_as_float(h & 0xFFFF0000u);
                    apl[tt][u] = bfpack(rb, ra);
                }
            }

            // ---- PV ----
#pragma unroll
            for (int tt = 0; tt < 4; tt++) {
#pragma unroll
                for (int e = 0; e < 4; e++) {
                    unsigned adr = VHIb + lmBase + tt*2048 + ((((unsigned)(2*e + laneHi)) ^ (unsigned)kx) << 4);
                    unsigned vh[4], vl[4];
                    ldm4t(vh, adr);
                    ldm4t(vl, adr + 8192);
                    mma16(o[2*e],   aph[tt], vh[0], vh[1]);
                    mma16(o[2*e],   apl[tt], vh[0], vh[1]);
                    mma16(o[2*e],   aph[tt], vl[0], vl[1]);
                    mma16(o[2*e+1], aph[tt], vh[2], vh[3]);
                    mma16(o[2*e+1], apl[tt], vh[2], vh[3]);
                    mma16(o[2*e+1], aph[tt], vl[2], vl[3]);
                }
            }
            __syncthreads();
        }

        // ---- segment epilogue: merge partials (pure addition) ----
        l0 += __shfl_xor_sync(0xffffffffu, l0, 1);
        l0 += __shfl_xor_sync(0xffffffffu, l0, 2);
        l1 += __shfl_xor_sync(0xffffffffu, l1, 1);
        l1 += __shfl_xor_sync(0xffffffffu, l1, 2);
        {
            float* o0 = g_O + (tokb + q0)*HD + 2*r;
            float* o1 = g_O + (tokb + q1)*HD + 2*r;
#pragma unroll
            for (int j = 0; j < 8; j++) {
                atomicAdd(o0 + 8*j,     o[j][0]);
                atomicAdd(o0 + 8*j + 1, o[j][1]);
                atomicAdd(o1 + 8*j,     o[j][2]);
                atomicAdd(o1 + 8*j + 1, o[j][3]);
            }
            if (r == 0) {
                atomicAdd(&g_L[tokb + q0], l0);
                atomicAdd(&g_L[tokb + q1], l1);
            }
        }
        t += ntl;
    }
}

// =========================================================================
// norm_out: out = g_O / g_L, then reset accumulators for the next replay.
// =========================================================================
__global__ void norm_out(float* __restrict__ out)
{
    int i = blockIdx.x*256 + threadIdx.x;        // float4 index; TOK*HD/4 total
    float4 v = ((const float4*)g_O)[i];
    float l = g_L[i >> 4];
    __syncthreads();                              // all row-mates read l before zeroing
    float inv = 1.0f / l;
    ((float4*)out)[i] = make_float4(v.x*inv, v.y*inv, v.z*inv, v.w*inv);
    ((float4*)g_O)[i] = make_float4(0.f, 0.f, 0.f, 0.f);
    if ((i & 15) == 0) g_L[i >> 4] = 0.f;
}

extern "C" void kernel_launch(void* const* d_in, const int* in_sizes, int n_in,
                              void* d_out, int out_size)
{
    const float* x   = (const float*)d_in[0];
    const float* wk1 = (const float*)d_in[1];
    const float* bk1 = (const float*)d_in[2];
    const float* wk2 = (const float*)d_in[3];
    const float* wq1 = (const float*)d_in[4];
    const float* bq1 = (const float*)d_in[5];
    const float* wq2 = (const float*)d_in[6];
    const float* wv1 = (const float*)d_in[7];
    const float* bv1 = (const float*)d_in[8];
    const float* wv2 = (const float*)d_in[9];

    cudaFuncSetAttribute(proj_mma, cudaFuncAttributeMaxDynamicSharedMemorySize, PSM_BYTES);
    cudaFuncSetAttribute(attn_split, cudaFuncAttributeMaxDynamicSharedMemorySize, ASM_BYTES);

    conv_w<<<96, 256>>>(wk1, wq1, wv1, wk2, wq2, wv2);
    proj_mma<<<TOK/64, 128, PSM_BYTES>>>(x, bk1, bq1, bv1);
    attn_split<<<NCTA, 128, ASM_BYTES>>>();
    norm_out<<<TOK*HD/4/256, 256>>>((float*)d_out);
}

// round 17
// speedup vs baseline: 1.4885x; 1.1663x over previous
#include <cuda_runtime.h>

#define SLEN 4096
#define NBATCH 8
#define TOK (NBATCH*SLEN)
#define EMB 1024
#define HD 64
#define HALF 32

#define TILES_PER_B 2080            // 64*65/2
#define TOTAL_TILES (NBATCH*TILES_PER_B)
#define NCTA 444                    // 148 SMs x 3 CTAs
#define UNIT 38                     // ceil(16640/444)

// Scratch (device globals: allocation-free rule; zero-initialized at load)
__device__ float g_Q[TOK*HD];
__device__ float g_O[TOK*HD];       // split-K fp32 accumulator
__device__ float g_L[TOK];          // split-K softmax denominators
// Per-64-key-tile image: [tile][Kh | Vh | Vl][64 keys][128B swizzled row] = 24KB
__device__ __align__(16) unsigned char g_IMG[(TOK/64) * 24576];
__device__ unsigned short g_W1h[96*1024];
__device__ unsigned short g_W1l[96*1024];
__device__ unsigned short g_W2h[192*32];
__device__ unsigned short g_W2l[192*32];

// ---------- helpers ----------
__device__ __forceinline__ unsigned smem_u32(const void* p) {
    unsigned a;
    asm("{ .reg .u64 t; cvta.to.shared.u64 t, %1; cvt.u32.u64 %0, t; }" : "=r"(a) : "l"(p));
    return a;
}
__device__ __forceinline__ float ex2f(float x) {
    float r;
    asm("ex2.approx.f32 %0, %1;" : "=f"(r) : "f"(x));
    return r;
}
__device__ __forceinline__ unsigned bfpack(float hi, float lo) {
    unsigned d;
    asm("cvt.rn.bf16x2.f32 %0, %1, %2;" : "=r"(d) : "f"(hi), "f"(lo));
    return d;
}
__device__ __forceinline__ void mma16(float* c, const unsigned* a, unsigned b0, unsigned b1) {
    asm("mma.sync.aligned.m16n8k16.row.col.f32.bf16.bf16.f32 "
        "{%0,%1,%2,%3}, {%4,%5,%6,%7}, {%8,%9}, {%0,%1,%2,%3};"
        : "+f"(c[0]), "+f"(c[1]), "+f"(c[2]), "+f"(c[3])
        : "r"(a[0]), "r"(a[1]), "r"(a[2]), "r"(a[3]), "r"(b0), "r"(b1));
}
__device__ __forceinline__ void ldm4(unsigned* r, unsigned addr) {
    asm volatile("ldmatrix.sync.aligned.m8n8.x4.shared.b16 {%0,%1,%2,%3}, [%4];"
                 : "=r"(r[0]), "=r"(r[1]), "=r"(r[2]), "=r"(r[3]) : "r"(addr));
}
__device__ __forceinline__ void ldm4t(unsigned* r, unsigned addr) {
    asm volatile("ldmatrix.sync.aligned.m8n8.x4.trans.shared.b16 {%0,%1,%2,%3}, [%4];"
                 : "=r"(r[0]), "=r"(r[1]), "=r"(r[2]), "=r"(r[3]) : "r"(addr));
}
__device__ __forceinline__ float2 ldsf2(unsigned addr) {
    float2 v;
    asm volatile("ld.shared.v2.f32 {%0,%1}, [%2];" : "=f"(v.x), "=f"(v.y) : "r"(addr));
    return v;
}
__device__ __forceinline__ void cpasync16(unsigned saddr, const void* gaddr) {
    asm volatile("cp.async.cg.shared.global [%0], [%1], 16;" :: "r"(saddr), "l"(gaddr) : "memory");
}
__device__ __forceinline__ void cp_commit() { asm volatile("cp.async.commit_group;" ::: "memory"); }
__device__ __forceinline__ void cp_wait0()  { asm volatile("cp.async.wait_group 0;" ::: "memory"); }

// =========================================================================
// conv_w: one-time weight transpose + bf16 hi/lo split.
// =========================================================================
__global__ void conv_w(
    const float* __restrict__ wk1, const float* __restrict__ wq1, const float* __restrict__ wv1,
    const float* __restrict__ wk2, const float* __restrict__ wq2, const float* __restrict__ wv2)
{
    int i = blockIdx.x*blockDim.x + threadIdx.x;
    int stride = gridDim.x*blockDim.x;
    for (int idx = i; idx < 96*1024; idx += stride) {
        int n = idx >> 10, k = idx & 1023;
        int p = n >> 5, h = n & 31;
        const float* w1 = (p == 0) ? wk1 : ((p == 1) ? wq1 : wv1);
        float v = w1[k*HALF + h];
        unsigned hb = bfpack(0.f, v) & 0xFFFFu;
        float res = v - __uint_as_float(hb << 16);
        g_W1h[idx] = (unsigned short)hb;
        g_W1l[idx] = (unsigned short)(bfpack(0.f, res) & 0xFFFFu);
    }
    for (int idx = i; idx < 192*32; idx += stride) {
        int row = idx >> 5, j = idx & 31;
        int p = row >> 6, h = row & 63;
        const float* w2 = (p == 0) ? wk2 : ((p == 1) ? wq2 : wv2);
        float v = w2[j*HD + h];
        unsigned hb = bfpack(0.f, v) & 0xFFFFu;
        float res = v - __uint_as_float(hb << 16);
        g_W2h[idx] = (unsigned short)hb;
        g_W2l[idx] = (unsigned short)(bfpack(0.f, res) & 0xFFFFu);
    }
}

// =========================================================================
// proj_mma v3: fully async staging (fixed W1 plane indexing — no modulo).
//   X slab cp.async'd as RAW fp32 (pitch 68 floats); A-fragments built in
//   registers (LDS + split). W1 planes cp.async'd (already bf16).
//   Double-buffered, 1 sync/slab.
// =========================================================================
#define PXF0 0
#define PXF1 17408
#define PW1A 34816          // H @ +0, L @ +12288
#define PW1B 59392
#define PW2H 83968
#define PW2L 99328
#define PSM_BYTES 114688

__device__ __forceinline__ void proj_stage(unsigned sb, int buf, const float* __restrict__ x,
                                           int tok0, int s, int tid)
{
    unsigned xfb = sb + (buf ? PXF1 : PXF0);
    const char* xsrc = (const char*)x + (long long)tok0*4096 + (long long)s*256;
#pragma unroll
    for (int it = 0; it < 8; it++) {
        int idx = tid + it*128;              // 1024 chunks: 64 rows x 16
        int row = idx >> 4, f = idx & 15;
        cpasync16(xfb + row*272 + f*16, xsrc + (long long)row*4096 + f*16);
    }
    unsigned w1b = sb + (buf ? PW1B : PW1A);
    const char* h1 = (const char*)g_W1h;
    const char* l1 = (const char*)g_W1l;
#pragma unroll
    for (int it = 0; it < 6; it++) {
        int idx = tid + it*128;              // 768 chunks/plane: 96 rows x 8
        int row = idx >> 3, f = idx & 7;
        unsigned off = w1b + row*128 + ((((unsigned)f) ^ (unsigned)(row & 7)) << 4);
        const char* gsrc = h1 + row*2048 + s*128 + f*16;
        cpasync16(off,          gsrc);
        cpasync16(off + 12288,  gsrc + (l1 - h1));
    }
    cp_commit();
}

__global__ __launch_bounds__(128, 2) void proj_mma(
    const float* __restrict__ x,
    const float* __restrict__ bk1, const float* __restrict__ bq1, const float* __restrict__ bv1)
{
    extern __shared__ __align__(1024) unsigned char dsm[];
    const unsigned sb = smem_u32(dsm);

    const int tid = threadIdx.x;
    const int w    = tid >> 5;
    const int lane = tid & 31;
    const int g = lane >> 2, r = lane & 3;
    const int laneKey = lane & 15, laneHi = lane >> 4;
    const int tok0 = blockIdx.x * 64;

    // ---- stage W2t once (pitch 80B rows, synchronous is fine) ----
#pragma unroll
    for (int it = 0; it < 6; it++) {
        int idx = tid + it*128;
        int row = idx >> 2, f = idx & 3;
        *(uint4*)(dsm + PW2H + row*80 + f*16) = *(const uint4*)(g_W2h + row*32 + 8*f);
        *(uint4*)(dsm + PW2L + row*80 + f*16) = *(const uint4*)(g_W2l + row*32 + 8*f);
    }

    float Cf[12][4];
#pragma unroll
    for (int nt = 0; nt < 12; nt++)
#pragma unroll
        for (int u = 0; u < 4; u++) Cf[nt][u] = 0.f;

    // prime slab 0
    proj_stage(sb, 0, x, tok0, 0, tid);

    const int rA = 16*w + g;
    const int rB = rA + 8;

    for (int s = 0; s < 16; s++) {
        cp_wait0();
        __syncthreads();                     // slab s resident; prior readers done
        const int buf = s & 1;
        const unsigned xfb = sb + (buf ? PXF1 : PXF0);
        const unsigned w1b = sb + (buf ? PW1B : PW1A);

        if (s + 1 < 16)
            proj_stage(sb, buf ^ 1, x, tok0, s + 1, tid);

        // ---- GEMM1: A-frags from raw fp32 X (LDS + register split) ----
#pragma unroll
        for (int c = 0; c < 4; c++) {
            int kb = 16*c + 2*r;
            float2 a0 = ldsf2(xfb + rA*272 + kb*4);
            float2 a1 = ldsf2(xfb + rB*272 + kb*4);
            float2 a2 = ldsf2(xfb + rA*272 + kb*4 + 32);
            float2 a3 = ldsf2(xfb + rB*272 + kb*4 + 32);
            unsigned axh[4], axl[4];
            axh[0] = bfpack(a0.y, a0.x);
            axl[0] = bfpack(a0.y - __uint_as_float(axh[0] & 0xFFFF0000u),
                            a0.x - __uint_as_float(axh[0] << 16));
            axh[1] = bfpack(a1.y, a1.x);
            axl[1] = bfpack(a1.y - __uint_as_float(axh[1] & 0xFFFF0000u),
                            a1.x - __uint_as_float(axh[1] << 16));
            axh[2] = bfpack(a2.y, a2.x);
            axl[2] = bfpack(a2.y - __uint_as_float(axh[2] & 0xFFFF0000u),
                            a2.x - __uint_as_float(axh[2] << 16));
            axh[3] = bfpack(a3.y, a3.x);
            axl[3] = bfpack(a3.y - __uint_as_float(axh[3] & 0xFFFF0000u),
                            a3.x - __uint_as_float(axh[3] << 16));
#pragma unroll
            for (int tp = 0; tp < 6; tp++) {
                unsigned adrB = w1b + (16*tp + laneKey)*128
                              + ((((unsigned)(2*c + laneHi)) ^ (unsigned)(laneKey & 7)) << 4);
                unsigned bh[4], bl[4];
                ldm4(bh, adrB);
                ldm4(bl, adrB + 12288);
                mma16(Cf[2*tp],   axh, bh[0], bh[2]);
                mma16(Cf[2*tp],   axl, bh[0], bh[2]);
                mma16(Cf[2*tp],   axh, bl[0], bl[2]);
                mma16(Cf[2*tp+1], axh, bh[1], bh[3]);
                mma16(Cf[2*tp+1], axl, bh[1], bh[3]);
                mma16(Cf[2*tp+1], axh, bl[1], bl[3]);
            }
        }
    }

    // ---- bias + tanh in registers ----
#pragma unroll
    for (int nt = 0; nt < 12; nt++) {
        int p = nt >> 2;
        int h0 = (nt & 3)*8 + 2*r;
        const float* b1 = (p == 0) ? bk1 : ((p == 1) ? bq1 : bv1);
        float bb0 = b1[h0], bb1 = b1[h0 + 1];
        Cf[nt][0] = tanhf(Cf[nt][0] + bb0);
        Cf[nt][1] = tanhf(Cf[nt][1] + bb1);
        Cf[nt][2] = tanhf(Cf[nt][2] + bb0);
        Cf[nt][3] = tanhf(Cf[nt][3] + bb1);
    }

    // ---- GEMM2 + epilogue (K: hi plane only; V: hi+lo planes) ----
    const int key0 = 16*w + g;
    unsigned char* img = g_IMG + (long long)(tok0 >> 6) * 24576;
#pragma unroll
    for (int p = 0; p < 3; p++) {
        float o2[8][4];
#pragma unroll
        for (int e = 0; e < 8; e++)
#pragma unroll
            for (int u = 0; u < 4; u++) o2[e][u] = 0.f;

#pragma unroll
        for (int kc = 0; kc < 2; kc++) {
            int nt0 = 4*p + 2*kc;
            unsigned ah[4], al[4];
#pragma unroll
            for (int u = 0; u < 4; u++) {
                int nt = nt0 + ((u & 2) ? 1 : 0);
                int v0 = (u & 1) ? 2 : 0;
                float pa = Cf[nt][v0], pb = Cf[nt][v0 + 1];
                unsigned hh = bfpack(pb, pa);
                ah[u] = hh;
                float ra = pa - __uint_as_float(hh << 16);
                float rb = pb - __uint_as_float(hh & 0xFFFF0000u);
                al[u] = bfpack(rb, ra);
            }
#pragma unroll
            for (int e2 = 0; e2 < 4; e2++) {
                unsigned adr = sb + PW2H + (p*64 + 16*e2 + laneKey)*80 + kc*32 + laneHi*16;
                unsigned bh[4], bl[4];
                ldm4(bh, adr);
                ldm4(bl, adr + (PW2L - PW2H));
                mma16(o2[2*e2],   ah, bh[0], bh[2]);
                mma16(o2[2*e2],   al, bh[0], bh[2]);
                mma16(o2[2*e2],   ah, bl[0], bl[2]);
                mma16(o2[2*e2+1], ah, bh[1], bh[3]);
                mma16(o2[2*e2+1], al, bh[1], bh[3]);
                mma16(o2[2*e2+1], ah, bl[1], bl[3]);
            }
        }

        if (p == 1) {            // Q stays fp32
            long long row0 = tok0 + key0;
#pragma unroll
            for (int e = 0; e < 8; e++) {
                int h0 = 8*e + 2*r;
                *(float2*)&g_Q[row0*HD + h0]       = make_float2(o2[e][0], o2[e][1]);
                *(float2*)&g_Q[(row0 + 8)*HD + h0] = make_float2(o2[e][2], o2[e][3]);
            }
        } else {
            int sw = (key0 & 7) << 4;
#pragma unroll
            for (int e = 0; e < 8; e++) {
                unsigned inn0 = key0*128     + (((unsigned)(e << 4)) ^ (unsigned)sw) + r*4;
                unsigned inn1 = (key0+8)*128 + (((unsigned)(e << 4)) ^ (unsigned)sw) + r*4;
                unsigned h0w = bfpack(o2[e][1], o2[e][0]);
                unsigned h1w = bfpack(o2[e][3], o2[e][2]);
                if (p == 0) {    // K: hi only
                    *(unsigned*)(img + inn0) = h0w;
                    *(unsigned*)(img + inn1) = h1w;
                } else {         // V: hi + lo
                    float ra = o2[e][0] - __uint_as_float(h0w << 16);
                    float rb = o2[e][1] - __uint_as_float(h0w & 0xFFFF0000u);
                    float rc = o2[e][2] - __uint_as_float(h1w << 16);
                    float rd = o2[e][3] - __uint_as_float(h1w & 0xFFFF0000u);
                    *(unsigned*)(img + 8192 + inn0)  = h0w;
                    *(unsigned*)(img + 8192 + inn1)  = h1w;
                    *(unsigned*)(img + 16384 + inn0) = bfpack(rb, ra);
                    *(unsigned*)(img + 16384 + inn1) = bfpack(rd, rc);
                }
            }
        }
    }
}

// =========================================================================
// attn_split v5: 2-term QK (K hi plane only), 24KB tile images.
// =========================================================================
#define ABUF 24576
#define ASM_BYTES 49152

__global__ __launch_bounds__(128, 3) void attn_split()
{
    extern __shared__ __align__(1024) unsigned char asm_[];
    const unsigned sb = smem_u32(asm_);

    const int tid  = threadIdx.x;
    const int w    = tid >> 5;
    const int lane = tid & 31;
    const int g    = lane >> 2;
    const int r    = lane & 3;
    const int laneKey = lane & 15;
    const int laneHi  = lane >> 4;
    const int kx      = laneKey & 7;
    const unsigned lmBase = laneKey * 128;
    const float SC = 0.1803368801111204f;    // 1/sqrt(64) * log2(e)

    int t  = blockIdx.x * UNIT;
    int t1 = t + UNIT; if (t1 > TOTAL_TILES) t1 = TOTAL_TILES;

    while (t < t1) {
        int b  = t / TILES_PER_B;
        int rr = t - b*TILES_PER_B;
        int qt = (int)((sqrtf(8.f*(float)rr + 1.f) - 1.f) * 0.5f);
        while ((qt+1)*(qt+2)/2 <= rr) qt++;
        while (qt*(qt+1)/2 > rr) qt--;
        int kt0 = rr - qt*(qt+1)/2;
        int ntl = qt + 1 - kt0;
        if (ntl > t1 - t) ntl = t1 - t;

        const long long tokb = (long long)b*SLEN;
        const int q0 = qt*64 + 16*w + g;
        const int q1 = q0 + 8;

        // ---- prime tile kt0 ----
        {
            const unsigned char* src = g_IMG + (long long)(b*64 + kt0) * 24576;
#pragma unroll
            for (int it = 0; it < 12; it++) {
                unsigned idx = (unsigned)(tid + it*128) * 16u;
                cpasync16(sb + idx, src + idx);
            }
            cp_commit();
        }

        // ---- Q fragments ----
        unsigned qhi[4][4], qlo[4][4];
        {
            const float* qA = g_Q + (tokb + q0)*HD;
            const float* qB = qA + 8*HD;
#pragma unroll
            for (int c = 0; c < 4; c++) {
#pragma unroll
                for (int u = 0; u < 4; u++) {
                    const float* src = (u & 1) ? qB : qA;
                    int d = 16*c + 2*r + ((u & 2) ? 8 : 0);
                    float2 xv = *(const float2*)(src + d);
                    float v0 = xv.x * SC, v1 = xv.y * SC;
                    unsigned h = bfpack(v1, v0);
                    qhi[c][u] = h;
                    float r0 = v0 - __uint_as_float(h << 16);
                    float r1 = v1 - __uint_as_float(h & 0xFFFF0000u);
                    qlo[c][u] = bfpack(r1, r0);
                }
            }
        }

        float o[8][4];
#pragma unroll
        for (int j = 0; j < 8; j++)
#pragma unroll
            for (int u = 0; u < 4; u++) o[j][u] = 0.f;
        float l0 = 0.f, l1 = 0.f;

        for (int i = 0; i < ntl; i++) {
            const int kt = kt0 + i;
            cp_wait0();
            __syncthreads();
            const unsigned cur  = sb + (unsigned)(i & 1) * ABUF;
            const unsigned KHIb = cur;
            const unsigned VHIb = cur + 8192;

            if (i + 1 < ntl) {
                const unsigned char* src = g_IMG + (long long)(b*64 + kt + 1) * 24576;
                unsigned dst = sb + (unsigned)((i + 1) & 1) * ABUF;
#pragma unroll
                for (int it = 0; it < 12; it++) {
                    unsigned idx = (unsigned)(tid + it*128) * 16u;
                    cpasync16(dst + idx, src + idx);
                }
                cp_commit();
            }

            // ---- QK: 2-term (K hi plane only; Q hi+lo) ----
            float s[8][4];
#pragma unroll
            for (int j = 0; j < 8; j++)
#pragma unroll
                for (int u = 0; u < 4; u++) s[j][u] = 0.f;

#pragma unroll
            for (int c = 0; c < 4; c++) {
#pragma unroll
                for (int tt = 0; tt < 4; tt++) {
                    unsigned adr = KHIb + lmBase + tt*2048 + ((((unsigned)(2*c + laneHi)) ^ (unsigned)kx) << 4);
                    unsigned kh[4];
                    ldm4(kh, adr);
                    mma16(s[2*tt],   qhi[c], kh[0], kh[2]);
                    mma16(s[2*tt],   qlo[c], kh[0], kh[2]);
                    mma16(s[2*tt+1], qhi[c], kh[1], kh[3]);
                    mma16(s[2*tt+1], qlo[c], kh[1], kh[3]);
                }
            }

            // ---- softmax (p = 2^s, no-max) + causal mask ----
            const int kb = kt*64;
            if (kt == qt) {
#pragma unroll
                for (int j = 0; j < 8; j++) {
                    int k0 = kb + 8*j + 2*r;
                    float p0 = (k0     > q0) ? 0.f : ex2f(fminf(s[j][0], 80.f));
                    float p1 = (k0 + 1 > q0) ? 0.f : ex2f(fminf(s[j][1], 80.f));
                    float p2 = (k0     > q1) ? 0.f : ex2f(fminf(s[j][2], 80.f));
                    float p3 = (k0 + 1 > q1) ? 0.f : ex2f(fminf(s[j][3], 80.f));
                    l0 += p0 + p1; l1 += p2 + p3;
                    s[j][0] = p0; s[j][1] = p1; s[j][2] = p2; s[j][3] = p3;
                }
            } else {
#pragma unroll
                for (int j = 0; j < 8; j++) {
                    float p0 = ex2f(fminf(s[j][0], 80.f));
                    float p1 = ex2f(fminf(s[j][1], 80.f));
                    float p2 = ex2f(fminf(s[j][2], 80.f));
                    float p3 = ex2f(fminf(s[j][3], 80.f));
                    l0 += p0 + p1; l1 += p2 + p3;
                    s[j][0] = p0; s[j][1] = p1; s[j][2] = p2; s[j][3] = p3;
                }
            }

            // ---- pack P (registers only) ----
            unsigned aph[4][4], apl[4][4];
#pragma unroll
            for (int tt = 0; tt < 4; tt++) {
#pragma unroll
                for (int u = 0; u < 4; u++) {
                    int j  = 2*tt + ((u & 2) ? 1 : 0);
                    int v0 = (u & 1) ? 2 : 0;
                    float pa = s[j][v0], pb = s[j][v0 + 1];
                    unsigned h = bfpack(pb, pa);
                    aph[tt][u] = h;
                    float ra = pa - __uint_as_float(h << 16);
                    float rb = pb - __uint_as_float(h & 0xFFFF0000u);
                    apl[tt][u] = bfpack(rb, ra);
                }
            }

            // ---- PV: 3-term (V hi+lo) ----
#pragma unroll
            for (int tt = 0; tt < 4; tt++) {
#pragma unroll
                for (int e = 0; e < 4; e++) {
                    unsigned adr = VHIb + lmBase + tt*2048 + ((((unsigned)(2*e + laneHi)) ^ (unsigned)kx) << 4);
                    unsigned vh[4], vl[4];
                    ldm4t(vh, adr);
                    ldm4t(vl, adr + 8192);
                    mma16(o[2*e],   aph[tt], vh[0], vh[1]);
                    mma16(o[2*e],   apl[tt], vh[0], vh[1]);
                    mma16(o[2*e],   aph[tt], vl[0], vl[1]);
                    mma16(o[2*e+1], aph[tt], vh[2], vh[3]);
                    mma16(o[2*e+1], apl[tt], vh[2], vh[3]);
                    mma16(o[2*e+1], aph[tt], vl[2], vl[3]);
                }
            }
            __syncthreads();
        }

        // ---- segment epilogue: merge partials (pure addition) ----
        l0 += __shfl_xor_sync(0xffffffffu, l0, 1);
        l0 += __shfl_xor_sync(0xffffffffu, l0, 2);
        l1 += __shfl_xor_sync(0xffffffffu, l1, 1);
        l1 += __shfl_xor_sync(0xffffffffu, l1, 2);
        {
            float* o0 = g_O + (tokb + q0)*HD + 2*r;
            float* o1 = g_O + (tokb + q1)*HD + 2*r;
#pragma unroll
            for (int j = 0; j < 8; j++) {
                atomicAdd(o0 + 8*j,     o[j][0]);
                atomicAdd(o0 + 8*j + 1, o[j][1]);
                atomicAdd(o1 + 8*j,     o[j][2]);
                atomicAdd(o1 + 8*j + 1, o[j][3]);
            }
            if (r == 0) {
                atomicAdd(&g_L[tokb + q0], l0);
                atomicAdd(&g_L[tokb + q1], l1);
            }
        }
        t += ntl;
    }
}

// =========================================================================
// norm_out: out = g_O / g_L, then reset accumulators for the next replay.
// =========================================================================
__global__ void norm_out(float* __restrict__ out)
{
    int i = blockIdx.x*256 + threadIdx.x;
    float4 v = ((const float4*)g_O)[i];
    float l = g_L[i >> 4];
    __syncthreads();
    float inv = 1.0f / l;
    ((float4*)out)[i] = make_float4(v.x*inv, v.y*inv, v.z*inv, v.w*inv);
    ((float4*)g_O)[i] = make_float4(0.f, 0.f, 0.f, 0.f);
    if ((i & 15) == 0) g_L[i >> 4] = 0.f;
}

extern "C" void kernel_launch(void* const* d_in, const int* in_sizes, int n_in,
                              void* d_out, int out_size)
{
    const float* x   = (const float*)d_in[0];
    const float* wk1 = (const float*)d_in[1];
    const float* bk1 = (const float*)d_in[2];
    const float* wk2 = (const float*)d_in[3];
    const float* wq1 = (const float*)d_in[4];
    const float* bq1 = (const float*)d_in[5];
    const float* wq2 = (const float*)d_in[6];
    const float* wv1 = (const float*)d_in[7];
    const float* bv1 = (const float*)d_in[8];
    const float* wv2 = (const float*)d_in[9];

    cudaFuncSetAttribute(proj_mma, cudaFuncAttributeMaxDynamicSharedMemorySize, PSM_BYTES);
    cudaFuncSetAttribute(attn_split, cudaFuncAttributeMaxDynamicSharedMemorySize, ASM_BYTES);

    conv_w<<<96, 256>>>(wk1, wq1, wv1, wk2, wq2, wv2);
    proj_mma<<<TOK/64, 128, PSM_BYTES>>>(x, bk1, bq1, bv1);
    attn_split<<<NCTA, 128, ASM_BYTES>>>();
    norm_out<<<TOK*HD/4/256, 256>>>((float*)d_out);
}